// round 10
// baseline (speedup 1.0000x reference)
#include <cuda_runtime.h>
#include <cuda_bf16.h>
#include <mma.h>
#include <cstdint>

using namespace nvcuda;

typedef unsigned long long u64;

#define Bsz    256
#define Ssz    512
#define Tsz    20
#define Esz    25
#define Hsz    128
#define SKIPsz 64
#define Gsz    512            // 4*H
#define NROWS  (Bsz*Ssz)      // 131072 ; row r = t*256 + b (t-major)

// ---------------- scratch (static device globals; no allocation) ----------
__device__ float g_xpool[(size_t)NROWS * Esz];        // [t*256+b][25]
__device__ float g_mask [(size_t)NROWS];              // [t*256+b]
__device__ float g_P    [(size_t)2 * NROWS * Gsz];    // [dir][t*256+b][512]  (NO bias)
__device__ float g_out  [(size_t)NROWS * 256];        // [b*512+t][256] (f|b)
__device__ float g_hf   [(size_t)Bsz * Hsz];          // final fwd h
__device__ float g_energy[(size_t)NROWS];             // [b*512+t]

// ---------------- f32x2 helpers -------------------------------------------
__device__ __forceinline__ u64 pk(float a, float b) {
    u64 r;
    asm("mov.b64 %0, {%1, %2};" : "=l"(r) : "r"(__float_as_uint(a)), "r"(__float_as_uint(b)));
    return r;
}
__device__ __forceinline__ void upk(u64 v, float& a, float& b) {
    unsigned lo, hi;
    asm("mov.b64 {%0, %1}, %2;" : "=r"(lo), "=r"(hi) : "l"(v));
    a = __uint_as_float(lo); b = __uint_as_float(hi);
}
__device__ __forceinline__ void fma2(u64& d, u64 a, u64 b) {
    asm("fma.rn.f32x2 %0, %1, %2, %0;" : "+l"(d) : "l"(a), "l"(b));
}
__device__ __forceinline__ float hadd(u64 v) {
    float a, b; upk(v, a, b); return a + b;
}

// ---------------- math helpers --------------------------------------------
__device__ __forceinline__ float sigf(float x) {
    return __fdividef(1.f, 1.f + __expf(-x));
}
__device__ __forceinline__ float tanhpr(float x) {
    return __fdividef(2.f, 1.f + __expf(-2.f * x)) - 1.f;
}

// ================= K1: embedding mean-pool + step mask =====================
__global__ void k_embed(const int* __restrict__ tags, const float* __restrict__ emb) {
    int g    = blockIdx.x * 8 + (threadIdx.x >> 5);
    int lane = threadIdx.x & 31;
    if (g >= NROWS) return;
    int b = g >> 9, s = g & 511;
    const int* tg = tags + (size_t)g * Tsz;
    float acc = 0.f; int cnt = 0; int first = 0;
    #pragma unroll
    for (int i = 0; i < Tsz; i++) {
        int tv = __ldg(tg + i);
        if (i == 0) first = tv;
        if (tv != 0) {
            cnt++;
            if (lane < Esz) acc += __ldg(emb + (size_t)tv * Esz + lane);
        }
    }
    int r = s * Bsz + b;
    if (lane < Esz) g_xpool[(size_t)r * Esz + lane] = acc / (cnt ? (float)cnt : 1.f);
    if (lane == 0)  g_mask[r] = (first != 0) ? 1.f : 0.f;
}

// ================= K2: prologue GEMM via wmma (bf16 2-split, HMMA) =========
#define PSM_AHI 0
#define PSM_ALO (256 * 96 * 2)
#define PSM_BHI (2 * 256 * 96 * 2)
#define PSM_BLO (2 * 256 * 96 * 2 + 96 * 256 * 2)
#define PSM_TOTAL (2 * 256 * 96 * 2 + 2 * 96 * 256 * 2)   // 196608 B
__global__ __launch_bounds__(512, 1)
void k_progemm(const float* __restrict__ skips,
               const float* __restrict__ Kf, const float* __restrict__ Skf,
               const float* __restrict__ Kb, const float* __restrict__ Skb) {
    extern __shared__ __align__(16) char psm[];
    __nv_bfloat16* Ahi = (__nv_bfloat16*)(psm + PSM_AHI);   // [256][96]
    __nv_bfloat16* Alo = (__nv_bfloat16*)(psm + PSM_ALO);
    __nv_bfloat16* Bhi = (__nv_bfloat16*)(psm + PSM_BHI);   // [96][256]
    __nv_bfloat16* Blo = (__nv_bfloat16*)(psm + PSM_BLO);

    int tid = threadIdx.x, d = blockIdx.y, bg = blockIdx.x;
    int w = tid >> 5;
    const float* Kw = d ? Kb : Kf;
    const float* Sw = d ? Skb : Skf;
    float* Pd = g_P + (size_t)d * NROWS * Gsz;

    #pragma unroll 1
    for (int half = 0; half < 2; half++) {
        __syncthreads();
        #pragma unroll 1
        for (int e = tid; e < 96 * 256; e += 512) {
            int k = e >> 8, n = e & 255;
            int col = half * 256 + n;
            float v = 0.f;
            if (k < Esz)      v = __ldg(Kw + (size_t)k * Gsz + col);
            else if (k < 89)  v = __ldg(Sw + (size_t)(k - Esz) * Gsz + col);
            __nv_bfloat16 h = __float2bfloat16(v);
            __nv_bfloat16 l = __float2bfloat16(v - __bfloat162float(h));
            Bhi[e] = h; Blo[e] = l;
        }
        #pragma unroll 1
        for (int mt = 0; mt < 8; mt++) {
            int r0 = (bg * 8 + mt) * 256;
            __syncthreads();
            #pragma unroll 1
            for (int e = tid; e < 256 * 96; e += 512) {
                int m = e / 96, k = e - m * 96;
                int r = r0 + m;
                int tt = r >> 8, bb2 = r & 255;
                float v = 0.f;
                if (k < Esz)      v = g_xpool[(size_t)r * Esz + k];
                else if (k < 89)  v = __ldg(skips + ((size_t)(bb2 << 9) + tt) * SKIPsz + (k - Esz));
                __nv_bfloat16 h = __float2bfloat16(v);
                __nv_bfloat16 l = __float2bfloat16(v - __bfloat162float(h));
                Ahi[e] = h; Alo[e] = l;
            }
            __syncthreads();
            const __nv_bfloat16* Aw_hi = Ahi + w * 16 * 96;
            const __nv_bfloat16* Aw_lo = Alo + w * 16 * 96;
            #pragma unroll 1
            for (int grp = 0; grp < 2; grp++) {
                wmma::fragment<wmma::accumulator, 16, 16, 16, float> acc[8];
                #pragma unroll
                for (int nf = 0; nf < 8; nf++) wmma::fill_fragment(acc[nf], 0.f);
                #pragma unroll 1
                for (int k = 0; k < 6; k++) {
                    wmma::fragment<wmma::matrix_a, 16, 16, 16, __nv_bfloat16, wmma::row_major> ah, al;
                    wmma::load_matrix_sync(ah, Aw_hi + k * 16, 96);
                    wmma::load_matrix_sync(al, Aw_lo + k * 16, 96);
                    #pragma unroll
                    for (int nf = 0; nf < 8; nf++) {
                        int n0 = (grp * 8 + nf) * 16;
                        wmma::fragment<wmma::matrix_b, 16, 16, 16, __nv_bfloat16, wmma::row_major> bh, bl;
                        wmma::load_matrix_sync(bh, Bhi + k * 16 * 256 + n0, 256);
                        wmma::load_matrix_sync(bl, Blo + k * 16 * 256 + n0, 256);
                        wmma::mma_sync(acc[nf], ah, bh, acc[nf]);
                        wmma::mma_sync(acc[nf], al, bh, acc[nf]);
                        wmma::mma_sync(acc[nf], ah, bl, acc[nf]);
                    }
                }
                #pragma unroll
                for (int nf = 0; nf < 8; nf++) {
                    int n0 = half * 256 + (grp * 8 + nf) * 16;
                    wmma::store_matrix_sync(Pd + (size_t)(r0 + w * 16) * Gsz + n0,
                                            acc[nf], Gsz, wmma::mem_row_major);
                }
            }
        }
    }
}

// ================= K3: LSTM recurrence (R3 layout + bias fold) ==============
#define LSTM_SMEM (98304 + 2048 + 8192 + 8192)
__global__ __launch_bounds__(512, 1)
void k_lstm(const float* __restrict__ Rf, const float* __restrict__ Rb,
            const float* __restrict__ bf, const float* __restrict__ bb) {
    extern __shared__ __align__(16) char smraw[];
    ulonglong2* R4  = (ulonglong2*)smraw;                    // [w*512 + j]
    u64*        h2s = (u64*)(smraw + 98304);                 // [p*4 + nb]
    float*      z_sm = (float*)(smraw + 98304 + 2048);       // [nb*512 + col]
    float*      msk  = (float*)(smraw + 98304 + 2048 + 8192);// [t*4 + nb]

    int j = threadIdx.x, d = blockIdx.y, bg = blockIdx.x;
    const float* R = d ? Rb : Rf;
    float bj = __ldg((d ? bb : bf) + j);

    u64 Rp[40];
    #pragma unroll
    for (int p = 0; p < 40; p++)
        Rp[p] = pk(__ldg(R + (2 * p) * Gsz + j), __ldg(R + (2 * p + 1) * Gsz + j));
    #pragma unroll 1
    for (int w = 0; w < 12; w++) {
        int r0 = 80 + 4 * w;
        ulonglong2 v;
        v.x = pk(__ldg(R + (r0 + 0) * Gsz + j), __ldg(R + (r0 + 1) * Gsz + j));
        v.y = pk(__ldg(R + (r0 + 2) * Gsz + j), __ldg(R + (r0 + 3) * Gsz + j));
        R4[w * 512 + j] = v;
    }
    if (j < 256) h2s[j] = 0ULL;
    for (int e = j; e < 2048; e += 512)
        msk[e] = g_mask[(e >> 2) * Bsz + 4 * bg + (e & 3)];

    int nb = j >> 7, jj = j & 127;
    int b  = 4 * bg + nb;
    float c = 0.f, hp = 0.f;

    const float* Pd = g_P + (size_t)d * NROWS * Gsz;
    int t = d ? (Ssz - 1) : 0;
    int dt = d ? -1 : 1;
    float pv0 = Pd[((size_t)(t * Bsz + 4 * bg + 0)) * Gsz + j] + bj;
    float pv1 = Pd[((size_t)(t * Bsz + 4 * bg + 1)) * Gsz + j] + bj;
    float pv2 = Pd[((size_t)(t * Bsz + 4 * bg + 2)) * Gsz + j] + bj;
    float pv3 = Pd[((size_t)(t * Bsz + 4 * bg + 3)) * Gsz + j] + bj;
    __syncthreads();

    #pragma unroll 1
    for (int i = 0; i < Ssz; i++) {
        u64 a0 = pk(pv0, 0.f), a1 = pk(pv1, 0.f), a2 = pk(pv2, 0.f), a3 = pk(pv3, 0.f);
        #pragma unroll
        for (int p = 0; p < 40; p++) {
            ulonglong2 ha = *(const ulonglong2*)&h2s[4 * p];
            ulonglong2 hb = *(const ulonglong2*)&h2s[4 * p + 2];
            fma2(a0, ha.x, Rp[p]); fma2(a1, ha.y, Rp[p]);
            fma2(a2, hb.x, Rp[p]); fma2(a3, hb.y, Rp[p]);
        }
        #pragma unroll
        for (int w = 0; w < 12; w++) {
            ulonglong2 rv = R4[w * 512 + j];
            int p0 = 40 + 2 * w;
            ulonglong2 ha0 = *(const ulonglong2*)&h2s[4 * p0];
            ulonglong2 hb0 = *(const ulonglong2*)&h2s[4 * p0 + 2];
            ulonglong2 ha1 = *(const ulonglong2*)&h2s[4 * p0 + 4];
            ulonglong2 hb1 = *(const ulonglong2*)&h2s[4 * p0 + 6];
            fma2(a0, ha0.x, rv.x); fma2(a1, ha0.y, rv.x);
            fma2(a2, hb0.x, rv.x); fma2(a3, hb0.y, rv.x);
            fma2(a0, ha1.x, rv.y); fma2(a1, ha1.y, rv.y);
            fma2(a2, hb1.x, rv.y); fma2(a3, hb1.y, rv.y);
        }
        z_sm[j]        = hadd(a0);
        z_sm[512 + j]  = hadd(a1);
        z_sm[1024 + j] = hadd(a2);
        z_sm[1536 + j] = hadd(a3);

        float pn0 = 0.f, pn1 = 0.f, pn2 = 0.f, pn3 = 0.f;
        int tn = t + dt;
        if (i < Ssz - 1) {
            pn0 = Pd[((size_t)(tn * Bsz + 4 * bg + 0)) * Gsz + j] + bj;
            pn1 = Pd[((size_t)(tn * Bsz + 4 * bg + 1)) * Gsz + j] + bj;
            pn2 = Pd[((size_t)(tn * Bsz + 4 * bg + 2)) * Gsz + j] + bj;
            pn3 = Pd[((size_t)(tn * Bsz + 4 * bg + 3)) * Gsz + j] + bj;
        }
        __syncthreads();
        {
            float m = msk[t * 4 + nb];
            const float* zz = z_sm + nb * 512;
            float zi = zz[jj], zf = zz[jj + 128], zg = zz[jj + 256], zo = zz[jj + 384];
            float cn = sigf(zf) * c + sigf(zi) * tanhpr(zg);
            float hn = sigf(zo) * tanhpr(cn);
            bool mm = (m != 0.f);
            float h2v = mm ? hn : hp;
            c  = mm ? cn : c;
            hp = h2v;
            g_out[(((size_t)b << 9) + t) * 256 + (d << 7) + jj] = h2v;
            if (d == 0 && i == Ssz - 1) g_hf[b * Hsz + jj] = h2v;
            float hnb = __shfl_down_sync(0xffffffffu, h2v, 1);
            if ((jj & 1) == 0) h2s[(jj >> 1) * 4 + nb] = pk(h2v, hnb);
        }
        __syncthreads();
        pv0 = pn0; pv1 = pn1; pv2 = pn2; pv3 = pn3; t = tn;
    }
}

// ================= K4: keys GEMM via wmma + qw + energy (fused) ============
// grid 512: blk -> batch b = blk>>1, rows r0 = blk*256. 256 threads (8 warps).
#define KSM_WKHI 0
#define KSM_WKLO 65536
#define KSM_AHI  131072
#define KSM_ALO  147456
#define KSM_K    163840
#define KSM_VEC  180224      // qb[128] | bkv[128] | Wev[128] | hfs[128]
#define KSM_TOTAL (180224 + 2048)
__global__ __launch_bounds__(256, 1)
void k_keys(const float* __restrict__ Wk, const float* __restrict__ bk,
            const float* __restrict__ Wq, const float* __restrict__ bq,
            const float* __restrict__ We, const float* __restrict__ be) {
    extern __shared__ __align__(16) char ksm[];
    __nv_bfloat16* Wkhi = (__nv_bfloat16*)(ksm + KSM_WKHI);  // [256][128]
    __nv_bfloat16* Wklo = (__nv_bfloat16*)(ksm + KSM_WKLO);
    __nv_bfloat16* Ahi  = (__nv_bfloat16*)(ksm + KSM_AHI);   // [32][256]
    __nv_bfloat16* Alo  = (__nv_bfloat16*)(ksm + KSM_ALO);
    float* keysm = (float*)(ksm + KSM_K);                    // [32][128]
    float* qb   = (float*)(ksm + KSM_VEC);
    float* bkv  = qb + 128;
    float* Wev  = bkv + 128;
    float* hfs  = Wev + 128;

    int tid = threadIdx.x, w = tid >> 5;
    int blk = blockIdx.x;
    int b = blk >> 1;
    int r0 = blk * 256;
    float bev = __ldg(be);

    // stage Wk splits [k][n]
    #pragma unroll 1
    for (int e = tid; e < 256 * 128; e += 256) {
        float v = __ldg(Wk + e);
        __nv_bfloat16 h = __float2bfloat16(v);
        Wkhi[e] = h;
        Wklo[e] = __float2bfloat16(v - __bfloat162float(h));
    }
    if (tid < 128) {
        hfs[tid] = g_hf[b * Hsz + tid];
        bkv[tid] = __ldg(bk + tid);
        Wev[tid] = __ldg(We + tid);
    }
    __syncthreads();
    if (tid < 128) {
        float acc = __ldg(bq + tid);
        #pragma unroll 8
        for (int k = 0; k < 128; k++) acc = fmaf(hfs[k], __ldg(Wq + k * Hsz + tid), acc);
        qb[tid] = acc;
    }
    __syncthreads();

    int mf  = w & 1;          // m-frag (16 rows)
    int nf0 = (w >> 1) * 2;   // two n-frags

    #pragma unroll 1
    for (int mt = 0; mt < 8; mt++) {
        int m0 = mt * 32;
        // stage A: 32 rows x 256 k, hi/lo
        #pragma unroll 1
        for (int e = tid; e < 32 * 256; e += 256) {
            int m = e >> 8, k = e & 255;
            float v = g_out[(size_t)(r0 + m0 + m) * 256 + k];
            __nv_bfloat16 h = __float2bfloat16(v);
            Ahi[e] = h;
            Alo[e] = __float2bfloat16(v - __bfloat162float(h));
        }
        __syncthreads();
        {
            wmma::fragment<wmma::accumulator, 16, 16, 16, float> acc0, acc1;
            wmma::fill_fragment(acc0, 0.f);
            wmma::fill_fragment(acc1, 0.f);
            const __nv_bfloat16* Am_hi = Ahi + mf * 16 * 256;
            const __nv_bfloat16* Am_lo = Alo + mf * 16 * 256;
            #pragma unroll 1
            for (int k = 0; k < 16; k++) {
                wmma::fragment<wmma::matrix_a, 16, 16, 16, __nv_bfloat16, wmma::row_major> ah, al;
                wmma::load_matrix_sync(ah, Am_hi + k * 16, 256);
                wmma::load_matrix_sync(al, Am_lo + k * 16, 256);
                wmma::fragment<wmma::matrix_b, 16, 16, 16, __nv_bfloat16, wmma::row_major> bh, bl;
                wmma::load_matrix_sync(bh, Wkhi + k * 16 * 128 + nf0 * 16, 128);
                wmma::load_matrix_sync(bl, Wklo + k * 16 * 128 + nf0 * 16, 128);
                wmma::mma_sync(acc0, ah, bh, acc0);
                wmma::mma_sync(acc0, al, bh, acc0);
                wmma::mma_sync(acc0, ah, bl, acc0);
                wmma::load_matrix_sync(bh, Wkhi + k * 16 * 128 + (nf0 + 1) * 16, 128);
                wmma::load_matrix_sync(bl, Wklo + k * 16 * 128 + (nf0 + 1) * 16, 128);
                wmma::mma_sync(acc1, ah, bh, acc1);
                wmma::mma_sync(acc1, al, bh, acc1);
                wmma::mma_sync(acc1, ah, bl, acc1);
            }
            wmma::store_matrix_sync(keysm + (size_t)(mf * 16) * 128 + nf0 * 16, acc0, 128, wmma::mem_row_major);
            wmma::store_matrix_sync(keysm + (size_t)(mf * 16) * 128 + (nf0 + 1) * 16, acc1, 128, wmma::mem_row_major);
        }
        __syncthreads();
        // energy: thread -> (row ro = tid>>3, col group g8 = tid&7 -> 16 cols)
        {
            int ro = tid >> 3, g8 = tid & 7;
            const float* kr = keysm + ro * 128 + g8 * 16;
            float v = 0.f;
            #pragma unroll
            for (int cidx = 0; cidx < 16; cidx++) {
                int col = g8 * 16 + cidx;
                v += Wev[col] * tanhpr(kr[cidx] + qb[col] + bkv[col]);
            }
            v += __shfl_down_sync(0xffffffffu, v, 4);
            v += __shfl_down_sync(0xffffffffu, v, 2);
            v += __shfl_down_sync(0xffffffffu, v, 1);
            if (g8 == 0) {
                int r2 = r0 + m0 + ro;
                int tt = r2 & 511;
                float m = g_mask[tt * Bsz + b];
                g_energy[r2] = v + bev - (1.f - m) * 1e9f;
            }
        }
        __syncthreads();
    }
}

// ================= K5: softmax over t + context =============================
__global__ __launch_bounds__(256, 1)
void k_softctx(float* __restrict__ out) {
    __shared__ float wsm[512];
    __shared__ float red[256];
    int b = blockIdx.x, tid = threadIdx.x;
    float e0 = g_energy[(size_t)b * 512 + tid];
    float e1 = g_energy[(size_t)b * 512 + 256 + tid];
    red[tid] = fmaxf(e0, e1);
    __syncthreads();
    #pragma unroll
    for (int o = 128; o > 0; o >>= 1) {
        if (tid < o) red[tid] = fmaxf(red[tid], red[tid + o]);
        __syncthreads();
    }
    float mx = red[0];
    __syncthreads();
    float x0 = __expf(e0 - mx), x1 = __expf(e1 - mx);
    wsm[tid] = x0; wsm[256 + tid] = x1;
    red[tid] = x0 + x1;
    __syncthreads();
    #pragma unroll
    for (int o = 128; o > 0; o >>= 1) {
        if (tid < o) red[tid] += red[tid + o];
        __syncthreads();
    }
    float inv = __fdividef(1.f, red[0]);

    const float* ob = g_out + (size_t)b * 512 * 256;
    float acc = 0.f;
    #pragma unroll 4
    for (int t = 0; t < 512; t++)
        acc = fmaf(wsm[t], __ldg(ob + (size_t)t * 256 + tid), acc);
    out[(size_t)b * 256 + tid] = acc * inv;
}

// ================= launch ===================================================
extern "C" void kernel_launch(void* const* d_in, const int* in_sizes, int n_in,
                              void* d_out, int out_size) {
    const int*   tags  = (const int*)  d_in[0];
    const float* skips = (const float*)d_in[1];
    const float* emb   = (const float*)d_in[2];
    const float* Kf    = (const float*)d_in[3];
    const float* Rf    = (const float*)d_in[4];
    const float* Skf   = (const float*)d_in[5];
    const float* bf    = (const float*)d_in[6];
    const float* Kb    = (const float*)d_in[7];
    const float* Rb    = (const float*)d_in[8];
    const float* Skb   = (const float*)d_in[9];
    const float* bb    = (const float*)d_in[10];
    const float* Wk    = (const float*)d_in[11];
    const float* bk    = (const float*)d_in[12];
    const float* Wq    = (const float*)d_in[13];
    const float* bq    = (const float*)d_in[14];
    const float* We    = (const float*)d_in[15];
    const float* be    = (const float*)d_in[16];
    float* out = (float*)d_out;

    cudaFuncSetAttribute(k_lstm, cudaFuncAttributeMaxDynamicSharedMemorySize, LSTM_SMEM);
    cudaFuncSetAttribute(k_progemm, cudaFuncAttributeMaxDynamicSharedMemorySize, PSM_TOTAL);
    cudaFuncSetAttribute(k_keys, cudaFuncAttributeMaxDynamicSharedMemorySize, KSM_TOTAL);

    k_embed<<<NROWS / 8, 256>>>(tags, emb);
    k_progemm<<<dim3(64, 2), 512, PSM_TOTAL>>>(skips, Kf, Skf, Kb, Skb);
    k_lstm<<<dim3(64, 2), 512, LSTM_SMEM>>>(Rf, Rb, bf, bb);
    k_keys<<<512, 256, KSM_TOTAL>>>(Wk, bk, Wq, bq, We, be);
    k_softctx<<<Bsz, 256>>>(out);
}

// round 11
// speedup vs baseline: 1.1371x; 1.1371x over previous
#include <cuda_runtime.h>
#include <cuda_bf16.h>
#include <mma.h>
#include <cstdint>

using namespace nvcuda;

typedef unsigned long long u64;

#define Bsz    256
#define Ssz    512
#define Tsz    20
#define Esz    25
#define Hsz    128
#define SKIPsz 64
#define Gsz    512            // 4*H
#define NROWS  (Bsz*Ssz)      // 131072 ; row r = t*256 + b (t-major)

// ---------------- scratch (static device globals; no allocation) ----------
__device__ float g_xpool[(size_t)NROWS * Esz];        // [t*256+b][25]
__device__ float g_mask [(size_t)NROWS];              // [t*256+b]
__device__ float g_P    [(size_t)2 * NROWS * Gsz];    // [dir][t*256+b][512]  (NO bias)
__device__ float g_out  [(size_t)NROWS * 256];        // [b*512+t][256] (f|b)
__device__ float g_hf   [(size_t)Bsz * Hsz];          // final fwd h
__device__ float g_qwq  [(size_t)Bsz * Hsz];          // h_fwd@Wq + bq
__device__ float g_energy[(size_t)NROWS];             // [b*512+t]

// ---------------- f32x2 helpers -------------------------------------------
__device__ __forceinline__ u64 pk(float a, float b) {
    u64 r;
    asm("mov.b64 %0, {%1, %2};" : "=l"(r) : "r"(__float_as_uint(a)), "r"(__float_as_uint(b)));
    return r;
}
__device__ __forceinline__ void upk(u64 v, float& a, float& b) {
    unsigned lo, hi;
    asm("mov.b64 {%0, %1}, %2;" : "=r"(lo), "=r"(hi) : "l"(v));
    a = __uint_as_float(lo); b = __uint_as_float(hi);
}
__device__ __forceinline__ void fma2(u64& d, u64 a, u64 b) {
    asm("fma.rn.f32x2 %0, %1, %2, %0;" : "+l"(d) : "l"(a), "l"(b));
}
__device__ __forceinline__ float hadd(u64 v) {
    float a, b; upk(v, a, b); return a + b;
}

// ---------------- math helpers --------------------------------------------
__device__ __forceinline__ float sigf(float x) {
    return __fdividef(1.f, 1.f + __expf(-x));
}
__device__ __forceinline__ float tanhpr(float x) {
    return __fdividef(2.f, 1.f + __expf(-2.f * x)) - 1.f;
}

// ================= K1: embedding mean-pool + step mask (split x2) ==========
__global__ void k_embed(const int* __restrict__ tags, const float* __restrict__ emb, int base) {
    int g    = base + blockIdx.x * 8 + (threadIdx.x >> 5);
    int lane = threadIdx.x & 31;
    int b = g >> 9, s = g & 511;
    const int* tg = tags + (size_t)g * Tsz;
    float acc = 0.f; int cnt = 0; int first = 0;
    #pragma unroll
    for (int i = 0; i < Tsz; i++) {
        int tv = __ldg(tg + i);
        if (i == 0) first = tv;
        if (tv != 0) {
            cnt++;
            if (lane < Esz) acc += __ldg(emb + (size_t)tv * Esz + lane);
        }
    }
    int r = s * Bsz + b;
    if (lane < Esz) g_xpool[(size_t)r * Esz + lane] = acc / (cnt ? (float)cnt : 1.f);
    if (lane == 0)  g_mask[r] = (first != 0) ? 1.f : 0.f;
}

// ================= K2: prologue GEMM via wmma (bf16 2-split, HMMA) =========
#define PSM_AHI 0
#define PSM_ALO (256 * 96 * 2)
#define PSM_BHI (2 * 256 * 96 * 2)
#define PSM_BLO (2 * 256 * 96 * 2 + 96 * 256 * 2)
#define PSM_TOTAL (2 * 256 * 96 * 2 + 2 * 96 * 256 * 2)   // 196608 B
__global__ __launch_bounds__(512, 1)
void k_progemm(const float* __restrict__ skips,
               const float* __restrict__ Kf, const float* __restrict__ Skf,
               const float* __restrict__ Kb, const float* __restrict__ Skb) {
    extern __shared__ __align__(16) char psm[];
    __nv_bfloat16* Ahi = (__nv_bfloat16*)(psm + PSM_AHI);   // [256][96]
    __nv_bfloat16* Alo = (__nv_bfloat16*)(psm + PSM_ALO);
    __nv_bfloat16* Bhi = (__nv_bfloat16*)(psm + PSM_BHI);   // [96][256]
    __nv_bfloat16* Blo = (__nv_bfloat16*)(psm + PSM_BLO);

    int tid = threadIdx.x, d = blockIdx.y, bg = blockIdx.x;
    int w = tid >> 5;
    const float* Kw = d ? Kb : Kf;
    const float* Sw = d ? Skb : Skf;
    float* Pd = g_P + (size_t)d * NROWS * Gsz;

    #pragma unroll 1
    for (int half = 0; half < 2; half++) {
        __syncthreads();
        #pragma unroll 1
        for (int e = tid; e < 96 * 256; e += 512) {
            int k = e >> 8, n = e & 255;
            int col = half * 256 + n;
            float v = 0.f;
            if (k < Esz)      v = __ldg(Kw + (size_t)k * Gsz + col);
            else if (k < 89)  v = __ldg(Sw + (size_t)(k - Esz) * Gsz + col);
            __nv_bfloat16 h = __float2bfloat16(v);
            __nv_bfloat16 l = __float2bfloat16(v - __bfloat162float(h));
            Bhi[e] = h; Blo[e] = l;
        }
        #pragma unroll 1
        for (int mt = 0; mt < 8; mt++) {
            int r0 = (bg * 8 + mt) * 256;
            __syncthreads();
            #pragma unroll 1
            for (int e = tid; e < 256 * 96; e += 512) {
                int m = e / 96, k = e - m * 96;
                int r = r0 + m;
                int tt = r >> 8, bb2 = r & 255;
                float v = 0.f;
                if (k < Esz)      v = g_xpool[(size_t)r * Esz + k];
                else if (k < 89)  v = __ldg(skips + ((size_t)(bb2 << 9) + tt) * SKIPsz + (k - Esz));
                __nv_bfloat16 h = __float2bfloat16(v);
                __nv_bfloat16 l = __float2bfloat16(v - __bfloat162float(h));
                Ahi[e] = h; Alo[e] = l;
            }
            __syncthreads();
            const __nv_bfloat16* Aw_hi = Ahi + w * 16 * 96;
            const __nv_bfloat16* Aw_lo = Alo + w * 16 * 96;
            #pragma unroll 1
            for (int grp = 0; grp < 2; grp++) {
                wmma::fragment<wmma::accumulator, 16, 16, 16, float> acc[8];
                #pragma unroll
                for (int nf = 0; nf < 8; nf++) wmma::fill_fragment(acc[nf], 0.f);
                #pragma unroll 1
                for (int k = 0; k < 6; k++) {
                    wmma::fragment<wmma::matrix_a, 16, 16, 16, __nv_bfloat16, wmma::row_major> ah, al;
                    wmma::load_matrix_sync(ah, Aw_hi + k * 16, 96);
                    wmma::load_matrix_sync(al, Aw_lo + k * 16, 96);
                    #pragma unroll
                    for (int nf = 0; nf < 8; nf++) {
                        int n0 = (grp * 8 + nf) * 16;
                        wmma::fragment<wmma::matrix_b, 16, 16, 16, __nv_bfloat16, wmma::row_major> bh, bl;
                        wmma::load_matrix_sync(bh, Bhi + k * 16 * 256 + n0, 256);
                        wmma::load_matrix_sync(bl, Blo + k * 16 * 256 + n0, 256);
                        wmma::mma_sync(acc[nf], ah, bh, acc[nf]);
                        wmma::mma_sync(acc[nf], al, bh, acc[nf]);
                        wmma::mma_sync(acc[nf], ah, bl, acc[nf]);
                    }
                }
                #pragma unroll
                for (int nf = 0; nf < 8; nf++) {
                    int n0 = half * 256 + (grp * 8 + nf) * 16;
                    wmma::store_matrix_sync(Pd + (size_t)(r0 + w * 16) * Gsz + n0,
                                            acc[nf], Gsz, wmma::mem_row_major);
                }
            }
        }
    }
}

// ================= K3: LSTM recurrence (quad layout, 1 barrier, fixed banks)
// grid (64, 2). 512 threads. Thread j: unit u=j>>2, gate g=j&3, owns column
// c = g*128 + u; z for 4 batches; warp-local 4x4 transpose -> gates for
// (u, batch g). h2s double-buffered; R smem tiles indexed BY j (conflict-free).
#define LSTM_SMEM (98304 + 4096 + 10240 + 8192)
__global__ __launch_bounds__(512, 1)
void k_lstm(const float* __restrict__ Rf, const float* __restrict__ Rb,
            const float* __restrict__ bf, const float* __restrict__ bb) {
    extern __shared__ __align__(16) char smraw[];
    ulonglong2* R4  = (ulonglong2*)smraw;                     // [w*512 + j] -> pairs 40+2w,41+2w of col c(j)
    u64*   h2s = (u64*)(smraw + 98304);                       // 2 bufs x [p*4 + nb]
    float* ztr = (float*)(smraw + 98304 + 4096);              // [j*5 + slot]
    float* msk = (float*)(smraw + 98304 + 4096 + 10240);      // [t*4 + nb]

    int j = threadIdx.x, d = blockIdx.y, bg = blockIdx.x;
    int u = j >> 2, g = j & 3;
    int c = g * 128 + u;
    const float* R = d ? Rb : Rf;
    float bj = __ldg((d ? bb : bf) + c);

    u64 Rp[40];
    #pragma unroll
    for (int p = 0; p < 40; p++)
        Rp[p] = pk(__ldg(R + (2 * p) * Gsz + c), __ldg(R + (2 * p + 1) * Gsz + c));
    #pragma unroll 1
    for (int w = 0; w < 12; w++) {
        int r0 = 80 + 4 * w;
        ulonglong2 v;
        v.x = pk(__ldg(R + (r0 + 0) * Gsz + c), __ldg(R + (r0 + 1) * Gsz + c));
        v.y = pk(__ldg(R + (r0 + 2) * Gsz + c), __ldg(R + (r0 + 3) * Gsz + c));
        R4[w * 512 + j] = v;   // indexed by j -> conflict-free LDS.128
    }
    if (j < 256) h2s[j] = 0ULL;   // buffer 0
    for (int e = j; e < 2048; e += 512)
        msk[e] = g_mask[(e >> 2) * Bsz + 4 * bg + (e & 3)];

    int myb = 4 * bg + g;
    float cst = 0.f, hp = 0.f;

    const float* Pd = g_P + (size_t)d * NROWS * Gsz;
    int t = d ? (Ssz - 1) : 0;
    int dt = d ? -1 : 1;
    float pv0 = Pd[((size_t)(t * Bsz + 4 * bg + 0)) * Gsz + c] + bj;
    float pv1 = Pd[((size_t)(t * Bsz + 4 * bg + 1)) * Gsz + c] + bj;
    float pv2 = Pd[((size_t)(t * Bsz + 4 * bg + 2)) * Gsz + c] + bj;
    float pv3 = Pd[((size_t)(t * Bsz + 4 * bg + 3)) * Gsz + c] + bj;
    __syncthreads();

    #pragma unroll 1
    for (int i = 0; i < Ssz; i++) {
        u64* hcur = h2s + (i & 1) * 256;
        u64* hnxt = h2s + ((i + 1) & 1) * 256;

        u64 a0 = pk(pv0, 0.f), a1 = pk(pv1, 0.f), a2 = pk(pv2, 0.f), a3 = pk(pv3, 0.f);
        #pragma unroll
        for (int p = 0; p < 40; p++) {
            ulonglong2 ha = *(const ulonglong2*)&hcur[4 * p];
            ulonglong2 hb = *(const ulonglong2*)&hcur[4 * p + 2];
            fma2(a0, ha.x, Rp[p]); fma2(a1, ha.y, Rp[p]);
            fma2(a2, hb.x, Rp[p]); fma2(a3, hb.y, Rp[p]);
        }
        #pragma unroll
        for (int w = 0; w < 12; w++) {
            ulonglong2 rv = R4[w * 512 + j];
            int p0 = 40 + 2 * w;
            ulonglong2 ha0 = *(const ulonglong2*)&hcur[4 * p0];
            ulonglong2 hb0 = *(const ulonglong2*)&hcur[4 * p0 + 2];
            ulonglong2 ha1 = *(const ulonglong2*)&hcur[4 * p0 + 4];
            ulonglong2 hb1 = *(const ulonglong2*)&hcur[4 * p0 + 6];
            fma2(a0, ha0.x, rv.x); fma2(a1, ha0.y, rv.x);
            fma2(a2, hb0.x, rv.x); fma2(a3, hb0.y, rv.x);
            fma2(a0, ha1.x, rv.y); fma2(a1, ha1.y, rv.y);
            fma2(a2, hb1.x, rv.y); fma2(a3, hb1.y, rv.y);
        }
        {
            float* zt = ztr + j * 5;
            zt[0] = hadd(a0); zt[1] = hadd(a1); zt[2] = hadd(a2); zt[3] = hadd(a3);
        }
        int tn = t + dt;
        float pn0 = 0.f, pn1 = 0.f, pn2 = 0.f, pn3 = 0.f;
        if (i < Ssz - 1) {
            pn0 = Pd[((size_t)(tn * Bsz + 4 * bg + 0)) * Gsz + c] + bj;
            pn1 = Pd[((size_t)(tn * Bsz + 4 * bg + 1)) * Gsz + c] + bj;
            pn2 = Pd[((size_t)(tn * Bsz + 4 * bg + 2)) * Gsz + c] + bj;
            pn3 = Pd[((size_t)(tn * Bsz + 4 * bg + 3)) * Gsz + c] + bj;
        }
        __syncwarp();
        {
            int base = (j & ~3) * 5 + g;
            float zi = ztr[base];
            float zf = ztr[base + 5];
            float zg = ztr[base + 10];
            float zo = ztr[base + 15];
            float m  = msk[t * 4 + g];
            float cn = sigf(zf) * cst + sigf(zi) * tanhpr(zg);
            float hn = sigf(zo) * tanhpr(cn);
            bool mm = (m != 0.f);
            float hv = mm ? hn : hp;
            cst = mm ? cn : cst;
            hp = hv;
            g_out[(((size_t)myb << 9) + t) * 256 + (d << 7) + u] = hv;
            if (d == 0 && i == Ssz - 1) g_hf[myb * Hsz + u] = hv;
            float hnext = __shfl_down_sync(0xffffffffu, hv, 4);
            if ((u & 1) == 0) hnxt[(u >> 1) * 4 + g] = pk(hv, hnext);
        }
        __syncthreads();
        pv0 = pn0; pv1 = pn1; pv2 = pn2; pv3 = pn3; t = tn;
    }
}

// ================= K4: queries = h_fwd @ Wq + bq ============================
__global__ void k_qw(const float* __restrict__ Wq, const float* __restrict__ bq) {
    __shared__ float hf[Hsz];
    int b = blockIdx.x, i = threadIdx.x;
    hf[i] = g_hf[b * Hsz + i];
    __syncthreads();
    float acc = __ldg(bq + i);
    #pragma unroll 8
    for (int k = 0; k < Hsz; k++) acc = fmaf(hf[k], __ldg(Wq + k * Hsz + i), acc);
    g_qwq[b * Hsz + i] = acc;
}

// ================= K5: keys GEMM + tanh + energy (R3 proven version) ========
__global__ __launch_bounds__(512, 1)
void k_keys(const float* __restrict__ Wk, const float* __restrict__ bk,
            const float* __restrict__ We, const float* __restrict__ be) {
    __shared__ __align__(16) u64 row2[4][128];
    __shared__ float qb[128], bks[128];
    __shared__ float partial[3][4][128];
    __shared__ float part2[4][4];

    int tid = threadIdx.x;
    int jc = tid & 127, qtr = tid >> 7;
    int blk = blockIdx.x;
    int b = blk >> 2;
    int r0 = blk * 128;

    u64 wq[32];
    #pragma unroll
    for (int i = 0; i < 32; i++) {
        int k0 = qtr * 64 + 2 * i;
        wq[i] = pk(__ldg(Wk + (size_t)k0 * Hsz + jc), __ldg(Wk + (size_t)(k0 + 1) * Hsz + jc));
    }
    if (tid < 128) { qb[tid] = g_qwq[b * Hsz + tid]; bks[tid] = __ldg(bk + tid); }
    float Wej = __ldg(We + jc);
    float bev = __ldg(be);
    __syncthreads();

    #pragma unroll 1
    for (int rr = 0; rr < 128; rr += 4) {
        {
            int ro = tid >> 7, p = tid & 127;
            const float2 v = *(const float2*)(g_out + (size_t)(r0 + rr + ro) * 256 + 2 * p);
            row2[ro][p] = pk(v.x, v.y);
        }
        __syncthreads();

        u64 a0 = pk(0.f, 0.f), a1 = a0, a2 = a0, a3 = a0;
        #pragma unroll
        for (int it = 0; it < 16; it++) {
            int p = qtr * 32 + 2 * it;
            u64 w0 = wq[2 * it], w1 = wq[2 * it + 1];
            ulonglong2 r_0 = *(const ulonglong2*)&row2[0][p];
            ulonglong2 r_1 = *(const ulonglong2*)&row2[1][p];
            ulonglong2 r_2 = *(const ulonglong2*)&row2[2][p];
            ulonglong2 r_3 = *(const ulonglong2*)&row2[3][p];
            fma2(a0, r_0.x, w0); fma2(a0, r_0.y, w1);
            fma2(a1, r_1.x, w0); fma2(a1, r_1.y, w1);
            fma2(a2, r_2.x, w0); fma2(a2, r_2.y, w1);
            fma2(a3, r_3.x, w0); fma2(a3, r_3.y, w1);
        }
        float acc[4] = { hadd(a0), hadd(a1), hadd(a2), hadd(a3) };
        if (qtr > 0) {
            #pragma unroll
            for (int ro = 0; ro < 4; ro++) partial[qtr - 1][ro][jc] = acc[ro];
        }
        __syncthreads();
        if (qtr == 0) {
            #pragma unroll
            for (int ro = 0; ro < 4; ro++) {
                float z = acc[ro] + partial[0][ro][jc] + partial[1][ro][jc] + partial[2][ro][jc]
                        + bks[jc] + qb[jc];
                float v = Wej * tanhpr(z);
                #pragma unroll
                for (int o = 16; o > 0; o >>= 1) v += __shfl_down_sync(0xffffffffu, v, o);
                if ((jc & 31) == 0) part2[ro][jc >> 5] = v;
            }
        }
        __syncthreads();
        if (tid < 4) {
            float e = part2[tid][0] + part2[tid][1] + part2[tid][2] + part2[tid][3] + bev;
            int r2 = r0 + rr + tid;
            int tt = r2 & 511;
            float m = g_mask[tt * Bsz + b];
            g_energy[r2] = e - (1.f - m) * 1e9f;
        }
        __syncthreads();
    }
}

// ================= K6: softmax over t + context =============================
__global__ __launch_bounds__(256, 1)
void k_softctx(float* __restrict__ out) {
    __shared__ float wsm[512];
    __shared__ float red[256];
    int b = blockIdx.x, tid = threadIdx.x;
    float e0 = g_energy[(size_t)b * 512 + tid];
    float e1 = g_energy[(size_t)b * 512 + 256 + tid];
    red[tid] = fmaxf(e0, e1);
    __syncthreads();
    #pragma unroll
    for (int o = 128; o > 0; o >>= 1) {
        if (tid < o) red[tid] = fmaxf(red[tid], red[tid + o]);
        __syncthreads();
    }
    float mx = red[0];
    __syncthreads();
    float x0 = __expf(e0 - mx), x1 = __expf(e1 - mx);
    wsm[tid] = x0; wsm[256 + tid] = x1;
    red[tid] = x0 + x1;
    __syncthreads();
    #pragma unroll
    for (int o = 128; o > 0; o >>= 1) {
        if (tid < o) red[tid] += red[tid + o];
        __syncthreads();
    }
    float inv = __fdividef(1.f, red[0]);

    const float* ob = g_out + (size_t)b * 512 * 256;
    float acc = 0.f;
    #pragma unroll 4
    for (int t = 0; t < 512; t++)
        acc = fmaf(wsm[t], __ldg(ob + (size_t)t * 256 + tid), acc);
    out[(size_t)b * 256 + tid] = acc * inv;
}

// ================= launch ===================================================
extern "C" void kernel_launch(void* const* d_in, const int* in_sizes, int n_in,
                              void* d_out, int out_size) {
    const int*   tags  = (const int*)  d_in[0];
    const float* skips = (const float*)d_in[1];
    const float* emb   = (const float*)d_in[2];
    const float* Kf    = (const float*)d_in[3];
    const float* Rf    = (const float*)d_in[4];
    const float* Skf   = (const float*)d_in[5];
    const float* bf    = (const float*)d_in[6];
    const float* Kb    = (const float*)d_in[7];
    const float* Rb    = (const float*)d_in[8];
    const float* Skb   = (const float*)d_in[9];
    const float* bb    = (const float*)d_in[10];
    const float* Wk    = (const float*)d_in[11];
    const float* bk    = (const float*)d_in[12];
    const float* Wq    = (const float*)d_in[13];
    const float* bq    = (const float*)d_in[14];
    const float* We    = (const float*)d_in[15];
    const float* be    = (const float*)d_in[16];
    float* out = (float*)d_out;

    cudaFuncSetAttribute(k_lstm, cudaFuncAttributeMaxDynamicSharedMemorySize, LSTM_SMEM);
    cudaFuncSetAttribute(k_progemm, cudaFuncAttributeMaxDynamicSharedMemorySize, PSM_TOTAL);

    k_embed<<<NROWS / 16, 256>>>(tags, emb, 0);
    k_embed<<<NROWS / 16, 256>>>(tags, emb, NROWS / 2);
    k_progemm<<<dim3(64, 2), 512, PSM_TOTAL>>>(skips, Kf, Skf, Kb, Skb);
    k_lstm<<<dim3(64, 2), 512, LSTM_SMEM>>>(Rf, Rb, bf, bb);   // launch #4 -> ncu
    k_qw<<<Bsz, Hsz>>>(Wq, bq);
    k_keys<<<1024, 512>>>(Wk, bk, We, be);
    k_softctx<<<Bsz, 256>>>(out);
}

// round 12
// speedup vs baseline: 1.2956x; 1.1394x over previous
#include <cuda_runtime.h>
#include <cuda_bf16.h>
#include <mma.h>
#include <cstdint>

using namespace nvcuda;

typedef unsigned long long u64;

#define Bsz    256
#define Ssz    512
#define Tsz    20
#define Esz    25
#define Hsz    128
#define SKIPsz 64
#define Gsz    512            // 4*H
#define NROWS  (Bsz*Ssz)      // 131072 ; row r = t*256 + b (t-major)

// ---------------- scratch (static device globals; no allocation) ----------
__device__ float g_xpool[(size_t)NROWS * Esz];        // [t*256+b][25]
__device__ float g_mask [(size_t)NROWS];              // [t*256+b]
__device__ float g_P    [(size_t)2 * NROWS * Gsz];    // [dir][t*256+b][512]  (NO bias)
__device__ float g_out  [(size_t)NROWS * 256];        // [b*512+t][256] (f|b)
__device__ float g_hf   [(size_t)Bsz * Hsz];          // final fwd h
__device__ float g_qwq  [(size_t)Bsz * Hsz];          // h_fwd@Wq + bq
__device__ float g_energy[(size_t)NROWS];             // [b*512+t]

// ---------------- f32x2 helpers -------------------------------------------
__device__ __forceinline__ u64 pk(float a, float b) {
    u64 r;
    asm("mov.b64 %0, {%1, %2};" : "=l"(r) : "r"(__float_as_uint(a)), "r"(__float_as_uint(b)));
    return r;
}
__device__ __forceinline__ void upk(u64 v, float& a, float& b) {
    unsigned lo, hi;
    asm("mov.b64 {%0, %1}, %2;" : "=r"(lo), "=r"(hi) : "l"(v));
    a = __uint_as_float(lo); b = __uint_as_float(hi);
}
__device__ __forceinline__ void fma2(u64& d, u64 a, u64 b) {
    asm("fma.rn.f32x2 %0, %1, %2, %0;" : "+l"(d) : "l"(a), "l"(b));
}
__device__ __forceinline__ float hadd(u64 v) {
    float a, b; upk(v, a, b); return a + b;
}

// ---------------- math helpers --------------------------------------------
__device__ __forceinline__ float sigf(float x) {
    return __fdividef(1.f, 1.f + __expf(-x));
}
__device__ __forceinline__ float tanhpr(float x) {
    return __fdividef(2.f, 1.f + __expf(-2.f * x)) - 1.f;
}

// ================= K1: embedding mean-pool + step mask (split x2) ==========
__global__ void k_embed(const int* __restrict__ tags, const float* __restrict__ emb, int base) {
    int g    = base + blockIdx.x * 8 + (threadIdx.x >> 5);
    int lane = threadIdx.x & 31;
    int b = g >> 9, s = g & 511;
    const int* tg = tags + (size_t)g * Tsz;
    float acc = 0.f; int cnt = 0; int first = 0;
    #pragma unroll
    for (int i = 0; i < Tsz; i++) {
        int tv = __ldg(tg + i);
        if (i == 0) first = tv;
        if (tv != 0) {
            cnt++;
            if (lane < Esz) acc += __ldg(emb + (size_t)tv * Esz + lane);
        }
    }
    int r = s * Bsz + b;
    if (lane < Esz) g_xpool[(size_t)r * Esz + lane] = acc / (cnt ? (float)cnt : 1.f);
    if (lane == 0)  g_mask[r] = (first != 0) ? 1.f : 0.f;
}

// ================= K2: prologue GEMM via wmma (bf16 2-split, HMMA) =========
#define PSM_AHI 0
#define PSM_ALO (256 * 96 * 2)
#define PSM_BHI (2 * 256 * 96 * 2)
#define PSM_BLO (2 * 256 * 96 * 2 + 96 * 256 * 2)
#define PSM_TOTAL (2 * 256 * 96 * 2 + 2 * 96 * 256 * 2)   // 196608 B
__global__ __launch_bounds__(512, 1)
void k_progemm(const float* __restrict__ skips,
               const float* __restrict__ Kf, const float* __restrict__ Skf,
               const float* __restrict__ Kb, const float* __restrict__ Skb) {
    extern __shared__ __align__(16) char psm[];
    __nv_bfloat16* Ahi = (__nv_bfloat16*)(psm + PSM_AHI);   // [256][96]
    __nv_bfloat16* Alo = (__nv_bfloat16*)(psm + PSM_ALO);
    __nv_bfloat16* Bhi = (__nv_bfloat16*)(psm + PSM_BHI);   // [96][256]
    __nv_bfloat16* Blo = (__nv_bfloat16*)(psm + PSM_BLO);

    int tid = threadIdx.x, d = blockIdx.y, bg = blockIdx.x;
    int w = tid >> 5;
    const float* Kw = d ? Kb : Kf;
    const float* Sw = d ? Skb : Skf;
    float* Pd = g_P + (size_t)d * NROWS * Gsz;

    #pragma unroll 1
    for (int half = 0; half < 2; half++) {
        __syncthreads();
        #pragma unroll 1
        for (int e = tid; e < 96 * 256; e += 512) {
            int k = e >> 8, n = e & 255;
            int col = half * 256 + n;
            float v = 0.f;
            if (k < Esz)      v = __ldg(Kw + (size_t)k * Gsz + col);
            else if (k < 89)  v = __ldg(Sw + (size_t)(k - Esz) * Gsz + col);
            __nv_bfloat16 h = __float2bfloat16(v);
            __nv_bfloat16 l = __float2bfloat16(v - __bfloat162float(h));
            Bhi[e] = h; Blo[e] = l;
        }
        #pragma unroll 1
        for (int mt = 0; mt < 8; mt++) {
            int r0 = (bg * 8 + mt) * 256;
            __syncthreads();
            #pragma unroll 1
            for (int e = tid; e < 256 * 96; e += 512) {
                int m = e / 96, k = e - m * 96;
                int r = r0 + m;
                int tt = r >> 8, bb2 = r & 255;
                float v = 0.f;
                if (k < Esz)      v = g_xpool[(size_t)r * Esz + k];
                else if (k < 89)  v = __ldg(skips + ((size_t)(bb2 << 9) + tt) * SKIPsz + (k - Esz));
                __nv_bfloat16 h = __float2bfloat16(v);
                __nv_bfloat16 l = __float2bfloat16(v - __bfloat162float(h));
                Ahi[e] = h; Alo[e] = l;
            }
            __syncthreads();
            const __nv_bfloat16* Aw_hi = Ahi + w * 16 * 96;
            const __nv_bfloat16* Aw_lo = Alo + w * 16 * 96;
            #pragma unroll 1
            for (int grp = 0; grp < 2; grp++) {
                wmma::fragment<wmma::accumulator, 16, 16, 16, float> acc[8];
                #pragma unroll
                for (int nf = 0; nf < 8; nf++) wmma::fill_fragment(acc[nf], 0.f);
                #pragma unroll 1
                for (int k = 0; k < 6; k++) {
                    wmma::fragment<wmma::matrix_a, 16, 16, 16, __nv_bfloat16, wmma::row_major> ah, al;
                    wmma::load_matrix_sync(ah, Aw_hi + k * 16, 96);
                    wmma::load_matrix_sync(al, Aw_lo + k * 16, 96);
                    #pragma unroll
                    for (int nf = 0; nf < 8; nf++) {
                        int n0 = (grp * 8 + nf) * 16;
                        wmma::fragment<wmma::matrix_b, 16, 16, 16, __nv_bfloat16, wmma::row_major> bh, bl;
                        wmma::load_matrix_sync(bh, Bhi + k * 16 * 256 + n0, 256);
                        wmma::load_matrix_sync(bl, Blo + k * 16 * 256 + n0, 256);
                        wmma::mma_sync(acc[nf], ah, bh, acc[nf]);
                        wmma::mma_sync(acc[nf], al, bh, acc[nf]);
                        wmma::mma_sync(acc[nf], ah, bl, acc[nf]);
                    }
                }
                #pragma unroll
                for (int nf = 0; nf < 8; nf++) {
                    int n0 = half * 256 + (grp * 8 + nf) * 16;
                    wmma::store_matrix_sync(Pd + (size_t)(r0 + w * 16) * Gsz + n0,
                                            acc[nf], Gsz, wmma::mem_row_major);
                }
            }
        }
    }
}

// ================= K3: LSTM recurrence (256 threads, 2 cols/thread) ========
// grid (64, 2). Thread u owns gate columns u and u+256 for 4 batches.
// R pairs 0..47 (rows 0..95) in regs per col (192 regs); pairs 48..63 smem.
// Proven R4 thread mapping; bias folded into P prefetch.
#define LSTM_SMEM (65536 + 2048 + 8192 + 8192)
__global__ __launch_bounds__(256, 1)
void k_lstm(const float* __restrict__ Rf, const float* __restrict__ Rb,
            const float* __restrict__ bf, const float* __restrict__ bb) {
    extern __shared__ __align__(16) char smraw[];
    ulonglong2* R4  = (ulonglong2*)smraw;                    // [w*512+col], w=0..7 -> pairs 48+2w,49+2w
    u64*   h2s = (u64*)(smraw + 65536);                      // [p*4+nb], p=0..63
    float* z_sm = (float*)(smraw + 65536 + 2048);            // [nb*512+col]
    float* msk  = (float*)(smraw + 65536 + 2048 + 8192);     // [t*4+nb]

    int u = threadIdx.x, d = blockIdx.y, bg = blockIdx.x;
    int colA = u, colB = u + 256;
    const float* R = d ? Rb : Rf;
    const float* bw = d ? bb : bf;
    float bjA = __ldg(bw + colA);
    float bjB = __ldg(bw + colB);

    u64 RA[48], RB[48];
    #pragma unroll
    for (int p = 0; p < 48; p++) {
        RA[p] = pk(__ldg(R + (2 * p) * Gsz + colA), __ldg(R + (2 * p + 1) * Gsz + colA));
        RB[p] = pk(__ldg(R + (2 * p) * Gsz + colB), __ldg(R + (2 * p + 1) * Gsz + colB));
    }
    #pragma unroll 1
    for (int e = u; e < 8 * 512; e += 256) {
        int w = e >> 9, col = e & 511;
        int r0 = 96 + 4 * w;
        ulonglong2 v;
        v.x = pk(__ldg(R + (r0 + 0) * Gsz + col), __ldg(R + (r0 + 1) * Gsz + col));
        v.y = pk(__ldg(R + (r0 + 2) * Gsz + col), __ldg(R + (r0 + 3) * Gsz + col));
        R4[e] = v;
    }
    h2s[u] = 0ULL;
    for (int e = u; e < 2048; e += 256)
        msk[e] = g_mask[(e >> 2) * Bsz + 4 * bg + (e & 3)];

    int nb = u >> 6, q = u & 63;
    int bq2 = 4 * bg + nb;
    float c0 = 0.f, c1 = 0.f, hp0 = 0.f, hp1 = 0.f;

    const float* Pd = g_P + (size_t)d * NROWS * Gsz;
    int t = d ? (Ssz - 1) : 0;
    int dt = d ? -1 : 1;
    float pvA0 = Pd[((size_t)(t * Bsz + 4 * bg + 0)) * Gsz + colA] + bjA;
    float pvA1 = Pd[((size_t)(t * Bsz + 4 * bg + 1)) * Gsz + colA] + bjA;
    float pvA2 = Pd[((size_t)(t * Bsz + 4 * bg + 2)) * Gsz + colA] + bjA;
    float pvA3 = Pd[((size_t)(t * Bsz + 4 * bg + 3)) * Gsz + colA] + bjA;
    float pvB0 = Pd[((size_t)(t * Bsz + 4 * bg + 0)) * Gsz + colB] + bjB;
    float pvB1 = Pd[((size_t)(t * Bsz + 4 * bg + 1)) * Gsz + colB] + bjB;
    float pvB2 = Pd[((size_t)(t * Bsz + 4 * bg + 2)) * Gsz + colB] + bjB;
    float pvB3 = Pd[((size_t)(t * Bsz + 4 * bg + 3)) * Gsz + colB] + bjB;
    __syncthreads();

    #pragma unroll 1
    for (int i = 0; i < Ssz; i++) {
        u64 aA0 = pk(pvA0, 0.f), aA1 = pk(pvA1, 0.f), aA2 = pk(pvA2, 0.f), aA3 = pk(pvA3, 0.f);
        u64 aB0 = pk(pvB0, 0.f), aB1 = pk(pvB1, 0.f), aB2 = pk(pvB2, 0.f), aB3 = pk(pvB3, 0.f);
        #pragma unroll
        for (int p = 0; p < 48; p++) {
            ulonglong2 ha = *(const ulonglong2*)&h2s[4 * p];
            ulonglong2 hb = *(const ulonglong2*)&h2s[4 * p + 2];
            fma2(aA0, ha.x, RA[p]); fma2(aA1, ha.y, RA[p]);
            fma2(aA2, hb.x, RA[p]); fma2(aA3, hb.y, RA[p]);
            fma2(aB0, ha.x, RB[p]); fma2(aB1, ha.y, RB[p]);
            fma2(aB2, hb.x, RB[p]); fma2(aB3, hb.y, RB[p]);
        }
        #pragma unroll
        for (int w = 0; w < 8; w++) {
            ulonglong2 rA = R4[w * 512 + colA];
            ulonglong2 rB = R4[w * 512 + colB];
            int p0 = 48 + 2 * w;
            ulonglong2 ha0 = *(const ulonglong2*)&h2s[4 * p0];
            ulonglong2 hb0 = *(const ulonglong2*)&h2s[4 * p0 + 2];
            ulonglong2 ha1 = *(const ulonglong2*)&h2s[4 * p0 + 4];
            ulonglong2 hb1 = *(const ulonglong2*)&h2s[4 * p0 + 6];
            fma2(aA0, ha0.x, rA.x); fma2(aA1, ha0.y, rA.x);
            fma2(aA2, hb0.x, rA.x); fma2(aA3, hb0.y, rA.x);
            fma2(aA0, ha1.x, rA.y); fma2(aA1, ha1.y, rA.y);
            fma2(aA2, hb1.x, rA.y); fma2(aA3, hb1.y, rA.y);
            fma2(aB0, ha0.x, rB.x); fma2(aB1, ha0.y, rB.x);
            fma2(aB2, hb0.x, rB.x); fma2(aB3, hb0.y, rB.x);
            fma2(aB0, ha1.x, rB.y); fma2(aB1, ha1.y, rB.y);
            fma2(aB2, hb1.x, rB.y); fma2(aB3, hb1.y, rB.y);
        }
        {
            z_sm[0 * 512 + colA] = hadd(aA0);
            z_sm[1 * 512 + colA] = hadd(aA1);
            z_sm[2 * 512 + colA] = hadd(aA2);
            z_sm[3 * 512 + colA] = hadd(aA3);
            z_sm[0 * 512 + colB] = hadd(aB0);
            z_sm[1 * 512 + colB] = hadd(aB1);
            z_sm[2 * 512 + colB] = hadd(aB2);
            z_sm[3 * 512 + colB] = hadd(aB3);
        }
        int tn = t + dt;
        float pnA0 = 0.f, pnA1 = 0.f, pnA2 = 0.f, pnA3 = 0.f;
        float pnB0 = 0.f, pnB1 = 0.f, pnB2 = 0.f, pnB3 = 0.f;
        if (i < Ssz - 1) {
            pnA0 = Pd[((size_t)(tn * Bsz + 4 * bg + 0)) * Gsz + colA] + bjA;
            pnA1 = Pd[((size_t)(tn * Bsz + 4 * bg + 1)) * Gsz + colA] + bjA;
            pnA2 = Pd[((size_t)(tn * Bsz + 4 * bg + 2)) * Gsz + colA] + bjA;
            pnA3 = Pd[((size_t)(tn * Bsz + 4 * bg + 3)) * Gsz + colA] + bjA;
            pnB0 = Pd[((size_t)(tn * Bsz + 4 * bg + 0)) * Gsz + colB] + bjB;
            pnB1 = Pd[((size_t)(tn * Bsz + 4 * bg + 1)) * Gsz + colB] + bjB;
            pnB2 = Pd[((size_t)(tn * Bsz + 4 * bg + 2)) * Gsz + colB] + bjB;
            pnB3 = Pd[((size_t)(tn * Bsz + 4 * bg + 3)) * Gsz + colB] + bjB;
        }
        __syncthreads();
        {
            float m = msk[t * 4 + nb];
            const float* zz = z_sm + nb * 512 + 2 * q;
            float2 zi = *(const float2*)(zz);
            float2 zf = *(const float2*)(zz + 128);
            float2 zg = *(const float2*)(zz + 256);
            float2 zo = *(const float2*)(zz + 384);
            float cn0 = sigf(zf.x) * c0 + sigf(zi.x) * tanhpr(zg.x);
            float hn0 = sigf(zo.x) * tanhpr(cn0);
            float cn1 = sigf(zf.y) * c1 + sigf(zi.y) * tanhpr(zg.y);
            float hn1 = sigf(zo.y) * tanhpr(cn1);
            bool mm = (m != 0.f);
            float h0 = mm ? hn0 : hp0; c0 = mm ? cn0 : c0;
            float h1 = mm ? hn1 : hp1; c1 = mm ? cn1 : c1;
            hp0 = h0; hp1 = h1;
            h2s[q * 4 + nb] = pk(h0, h1);
            *(float2*)(g_out + ((((size_t)bq2 << 9) + t)) * 256 + (d << 7) + 2 * q) = make_float2(h0, h1);
            if (d == 0 && i == Ssz - 1) {
                g_hf[bq2 * Hsz + 2 * q]     = h0;
                g_hf[bq2 * Hsz + 2 * q + 1] = h1;
            }
        }
        __syncthreads();
        pvA0 = pnA0; pvA1 = pnA1; pvA2 = pnA2; pvA3 = pnA3;
        pvB0 = pnB0; pvB1 = pnB1; pvB2 = pnB2; pvB3 = pnB3;
        t = tn;
    }
}

// ================= K4: queries = h_fwd @ Wq + bq ============================
__global__ void k_qw(const float* __restrict__ Wq, const float* __restrict__ bq) {
    __shared__ float hf[Hsz];
    int b = blockIdx.x, i = threadIdx.x;
    hf[i] = g_hf[b * Hsz + i];
    __syncthreads();
    float acc = __ldg(bq + i);
    #pragma unroll 8
    for (int k = 0; k < Hsz; k++) acc = fmaf(hf[k], __ldg(Wq + k * Hsz + i), acc);
    g_qwq[b * Hsz + i] = acc;
}

// ================= K5: keys GEMM + tanh + energy (R3 proven version) ========
__global__ __launch_bounds__(512, 1)
void k_keys(const float* __restrict__ Wk, const float* __restrict__ bk,
            const float* __restrict__ We, const float* __restrict__ be) {
    __shared__ __align__(16) u64 row2[4][128];
    __shared__ float qb[128], bks[128];
    __shared__ float partial[3][4][128];
    __shared__ float part2[4][4];

    int tid = threadIdx.x;
    int jc = tid & 127, qtr = tid >> 7;
    int blk = blockIdx.x;
    int b = blk >> 2;
    int r0 = blk * 128;

    u64 wq[32];
    #pragma unroll
    for (int i = 0; i < 32; i++) {
        int k0 = qtr * 64 + 2 * i;
        wq[i] = pk(__ldg(Wk + (size_t)k0 * Hsz + jc), __ldg(Wk + (size_t)(k0 + 1) * Hsz + jc));
    }
    if (tid < 128) { qb[tid] = g_qwq[b * Hsz + tid]; bks[tid] = __ldg(bk + tid); }
    float Wej = __ldg(We + jc);
    float bev = __ldg(be);
    __syncthreads();

    #pragma unroll 1
    for (int rr = 0; rr < 128; rr += 4) {
        {
            int ro = tid >> 7, p = tid & 127;
            const float2 v = *(const float2*)(g_out + (size_t)(r0 + rr + ro) * 256 + 2 * p);
            row2[ro][p] = pk(v.x, v.y);
        }
        __syncthreads();

        u64 a0 = pk(0.f, 0.f), a1 = a0, a2 = a0, a3 = a0;
        #pragma unroll
        for (int it = 0; it < 16; it++) {
            int p = qtr * 32 + 2 * it;
            u64 w0 = wq[2 * it], w1 = wq[2 * it + 1];
            ulonglong2 r_0 = *(const ulonglong2*)&row2[0][p];
            ulonglong2 r_1 = *(const ulonglong2*)&row2[1][p];
            ulonglong2 r_2 = *(const ulonglong2*)&row2[2][p];
            ulonglong2 r_3 = *(const ulonglong2*)&row2[3][p];
            fma2(a0, r_0.x, w0); fma2(a0, r_0.y, w1);
            fma2(a1, r_1.x, w0); fma2(a1, r_1.y, w1);
            fma2(a2, r_2.x, w0); fma2(a2, r_2.y, w1);
            fma2(a3, r_3.x, w0); fma2(a3, r_3.y, w1);
        }
        float acc[4] = { hadd(a0), hadd(a1), hadd(a2), hadd(a3) };
        if (qtr > 0) {
            #pragma unroll
            for (int ro = 0; ro < 4; ro++) partial[qtr - 1][ro][jc] = acc[ro];
        }
        __syncthreads();
        if (qtr == 0) {
            #pragma unroll
            for (int ro = 0; ro < 4; ro++) {
                float z = acc[ro] + partial[0][ro][jc] + partial[1][ro][jc] + partial[2][ro][jc]
                        + bks[jc] + qb[jc];
                float v = Wej * tanhpr(z);
                #pragma unroll
                for (int o = 16; o > 0; o >>= 1) v += __shfl_down_sync(0xffffffffu, v, o);
                if ((jc & 31) == 0) part2[ro][jc >> 5] = v;
            }
        }
        __syncthreads();
        if (tid < 4) {
            float e = part2[tid][0] + part2[tid][1] + part2[tid][2] + part2[tid][3] + bev;
            int r2 = r0 + rr + tid;
            int tt = r2 & 511;
            float m = g_mask[tt * Bsz + b];
            g_energy[r2] = e - (1.f - m) * 1e9f;
        }
        __syncthreads();
    }
}

// ================= K6: softmax over t + context =============================
__global__ __launch_bounds__(256, 1)
void k_softctx(float* __restrict__ out) {
    __shared__ float wsm[512];
    __shared__ float red[256];
    int b = blockIdx.x, tid = threadIdx.x;
    float e0 = g_energy[(size_t)b * 512 + tid];
    float e1 = g_energy[(size_t)b * 512 + 256 + tid];
    red[tid] = fmaxf(e0, e1);
    __syncthreads();
    #pragma unroll
    for (int o = 128; o > 0; o >>= 1) {
        if (tid < o) red[tid] = fmaxf(red[tid], red[tid + o]);
        __syncthreads();
    }
    float mx = red[0];
    __syncthreads();
    float x0 = __expf(e0 - mx), x1 = __expf(e1 - mx);
    wsm[tid] = x0; wsm[256 + tid] = x1;
    red[tid] = x0 + x1;
    __syncthreads();
    #pragma unroll
    for (int o = 128; o > 0; o >>= 1) {
        if (tid < o) red[tid] += red[tid + o];
        __syncthreads();
    }
    float inv = __fdividef(1.f, red[0]);

    const float* ob = g_out + (size_t)b * 512 * 256;
    float acc = 0.f;
    #pragma unroll 4
    for (int t = 0; t < 512; t++)
        acc = fmaf(wsm[t], __ldg(ob + (size_t)t * 256 + tid), acc);
    out[(size_t)b * 256 + tid] = acc * inv;
}

// ================= launch ===================================================
extern "C" void kernel_launch(void* const* d_in, const int* in_sizes, int n_in,
                              void* d_out, int out_size) {
    const int*   tags  = (const int*)  d_in[0];
    const float* skips = (const float*)d_in[1];
    const float* emb   = (const float*)d_in[2];
    const float* Kf    = (const float*)d_in[3];
    const float* Rf    = (const float*)d_in[4];
    const float* Skf   = (const float*)d_in[5];
    const float* bf    = (const float*)d_in[6];
    const float* Kb    = (const float*)d_in[7];
    const float* Rb    = (const float*)d_in[8];
    const float* Skb   = (const float*)d_in[9];
    const float* bb    = (const float*)d_in[10];
    const float* Wk    = (const float*)d_in[11];
    const float* bk    = (const float*)d_in[12];
    const float* Wq    = (const float*)d_in[13];
    const float* bq    = (const float*)d_in[14];
    const float* We    = (const float*)d_in[15];
    const float* be    = (const float*)d_in[16];
    float* out = (float*)d_out;

    cudaFuncSetAttribute(k_lstm, cudaFuncAttributeMaxDynamicSharedMemorySize, LSTM_SMEM);
    cudaFuncSetAttribute(k_progemm, cudaFuncAttributeMaxDynamicSharedMemorySize, PSM_TOTAL);

    k_embed<<<NROWS / 16, 256>>>(tags, emb, 0);
    k_embed<<<NROWS / 16, 256>>>(tags, emb, NROWS / 2);
    k_progemm<<<dim3(64, 2), 512, PSM_TOTAL>>>(skips, Kf, Skf, Kb, Skb);
    k_lstm<<<dim3(64, 2), 256, LSTM_SMEM>>>(Rf, Rb, bf, bb);   // launch #4 -> ncu
    k_qw<<<Bsz, Hsz>>>(Wq, bq);
    k_keys<<<1024, 512>>>(Wk, bk, We, be);
    k_softctx<<<Bsz, 256>>>(out);
}